// round 2
// baseline (speedup 1.0000x reference)
#include <cuda_runtime.h>
#include <cuda_bf16.h>

#define HNUM 256
#define WNUM 256
#define MC   128
#define RR   1024
#define TT   512
#define BINL 0.02f

// output layout (all float32, concat of reference tuple, row-major each)
#define N_MR   (MC * RR)                         // 131072
#define OFF_O  0LL
#define OFF_D  ((long long)N_MR * 3)
#define OFF_T  ((long long)N_MR * 6)
#define OFF_XY ((long long)N_MR * 6 + (long long)N_MR * TT)

// per-m scratch (allocation-free: device globals)
__device__ int   g_y[MC], g_x[MC], g_flag[MC];
__device__ float g_org[MC][3], g_lvec[MC][3];
__device__ float g_l[MC], g_eff[MC], g_d1d4[MC];

__global__ void k_pre(const float* __restrict__ laser_pos,
                      const float* __restrict__ camera_pos,
                      const float* __restrict__ laser_origin,
                      const float* __restrict__ camera_origin,
                      const int* __restrict__ idx_perm)
{
    int m = threadIdx.x;
    if (m >= MC) return;

    int idx = idx_perm[m];
    // clamp defensively so a bad read degrades to wrong values, not a crash
    if (idx < 0) idx = 0;
    if (idx >= HNUM * WNUM) idx = HNUM * WNUM - 1;
    int y = idx / WNUM;
    int x = idx % WNUM;
    if (m == 0) { y = HNUM / 2; x = WNUM / 2; }

    const float* lp = laser_pos  + ((long long)y * WNUM + x) * 3;
    const float* cp = camera_pos + ((long long)y * WNUM + x) * 3;
    float lp0 = lp[0], lp1 = lp[1], lp2 = lp[2];
    float cp0 = cp[0], cp1 = cp[1], cp2 = cp[2];

    float a0 = lp0 - laser_origin[0];
    float a1 = lp1 - laser_origin[1];
    float a2 = lp2 - laser_origin[2];
    float d1 = sqrtf(a0 * a0 + a1 * a1 + a2 * a2);

    float b0 = cp0 - camera_origin[0];
    float b1 = cp1 - camera_origin[1];
    float b2 = cp2 - camera_origin[2];
    float d4 = sqrtf(b0 * b0 + b1 * b1 + b2 * b2);

    float v0 = lp0 - cp0, v1 = lp1 - cp1, v2 = lp2 - cp2;
    float l  = sqrtf(v0 * v0 + v1 * v1 + v2 * v2);
    float inv = 1.0f / fmaxf(l, 1e-12f);

    // idx_offset = ceil((|lp-cp| - (d1+d4)) / BIN_LEN); eff = mod(offset, T) (python semantics)
    float off_f = ceilf((l - (d1 + d4)) / BINL);
    int   off   = (int)off_f;
    int   eff   = ((off % TT) + TT) % TT;

    g_y[m] = y;  g_x[m] = x;
    g_org[m][0] = cp0; g_org[m][1] = cp1; g_org[m][2] = cp2;
    g_lvec[m][0] = v0 * inv; g_lvec[m][1] = v1 * inv; g_lvec[m][2] = v2 * inv;
    g_l[m]    = l;
    g_eff[m]  = (float)eff;
    g_d1d4[m] = d1 + d4;
    g_flag[m] = 0;
}

__global__ void __launch_bounds__(128) k_main(const float* __restrict__ dirs,
                                              float* __restrict__ out)
{
    int b = blockIdx.x;            // 0 .. MC*RR-1
    int m = b >> 10;               // / RR
    int r = b & (RR - 1);
    int tid = threadIdx.x;         // 128 threads, 4 tau-bins each

    float l   = g_l[m];
    float eff = g_eff[m];
    float lv0 = g_lvec[m][0], lv1 = g_lvec[m][1], lv2 = g_lvec[m][2];
    float e0  = dirs[r * 3 + 0], e1 = dirs[r * 3 + 1], e2 = dirs[r * 3 + 2];

    // dx = directions[r] . lvec[m], strict left-to-right f32 (no FMA)
    float dx  = __fadd_rn(__fadd_rn(__fmul_rn(e0, lv0), __fmul_rn(e1, lv1)),
                          __fmul_rn(e2, lv2));
    float dx2 = __fmul_rn(dx, dx);
    float dy  = sqrtf(__fsub_rn(1.0f, dx2));   // NaN if dx^2 > 1 (must propagate, per reference)
    float dy2 = __fmul_rn(dy, dy);
    float l2  = __fmul_rn(l, l);
    float dxl = __fmul_rn(dx, l);

    int t0 = tid * 4;
    float res[4];
    bool anynan = false;

#pragma unroll
    for (int j = 0; j < 4; ++j) {
        float tf   = (float)(t0 + j);
        float tau  = __fmul_rn(BINL, fmaxf(tf, eff));
        float tau2 = __fmul_rn(tau, tau);
        float diff = __fsub_rn(tau2, l2);
        float num  = __fmul_rn(__fadd_rn(dxl, tau), diff);
        float den  = __fmul_rn(2.0f, __fadd_rn(__fmul_rn(dx2, diff),
                                               __fmul_rn(dy2, tau2)));
        float q    = __fdiv_rn(num, den);
        if (q != q) anynan = true;      // isnan
        res[j] = q;
    }

    float4* dst = (float4*)(out + OFF_T + (long long)b * TT + t0);
    *dst = make_float4(res[0], res[1], res[2], res[3]);

    // per-m NaN flag (any (r,t) NaN -> whole row replaced by t_conf in k_fix)
    if (__syncthreads_or((int)anynan)) {
        if (tid == 0) g_flag[m] = 1;   // idempotent racy store is fine
    }

    // small outputs
    if (tid < 3) {
        out[OFF_O + (long long)b * 3 + tid] = g_org[m][tid];
        out[OFF_D + (long long)b * 3 + tid] = (tid == 0 ? e0 : (tid == 1 ? e1 : e2));
    }
    if (tid < 2) {
        out[OFF_XY + (long long)b * 2 + tid] = (float)(tid == 0 ? g_y[m] : g_x[m]);
    }
}

// Rewrite whole (R,T) slab of flagged rows with t_conf (rare / usually no-op).
__global__ void __launch_bounds__(128) k_fix(float* __restrict__ out)
{
    int m = blockIdx.x;
    if (!g_flag[m]) return;

    float d1d4 = g_d1d4[m];
    int tid = threadIdx.x;
    int t0 = tid * 4;
    float res[4];
#pragma unroll
    for (int j = 0; j < 4; ++j) {
        float tau0 = __fmul_rn((float)(t0 + j), BINL);
        float d    = __fsub_rn(tau0, d1d4);
        if (d <= 0.0f) d = 1e-6f;
        res[j] = __fmul_rn(d, 0.5f);
    }
    float4 v4 = make_float4(res[0], res[1], res[2], res[3]);
    for (int r = blockIdx.y; r < RR; r += gridDim.y) {
        *(float4*)(out + OFF_T + ((long long)m * RR + r) * TT + t0) = v4;
    }
}

extern "C" void kernel_launch(void* const* d_in, const int* in_sizes, int n_in,
                              void* d_out, int out_size)
{
    // Identify inputs by element count (robust to metadata ordering):
    //   laser_pos / camera_pos : 196608 each (laser first)
    //   laser_origin / camera_origin : 3 each (laser first)
    //   directions : 3072
    //   idx_perm : 128
    const float* big[2]   = {nullptr, nullptr};
    const float* small3[2]= {nullptr, nullptr};
    const float* dirs     = nullptr;
    const int*   idxp     = nullptr;
    int nbig = 0, nsmall = 0;
    for (int i = 0; i < n_in; ++i) {
        int s = in_sizes[i];
        if (s == HNUM * WNUM * 3) { if (nbig < 2) big[nbig++] = (const float*)d_in[i]; }
        else if (s == 3)          { if (nsmall < 2) small3[nsmall++] = (const float*)d_in[i]; }
        else if (s == RR * 3)     { dirs = (const float*)d_in[i]; }
        else if (s == MC)         { idxp = (const int*)d_in[i]; }
    }
    const float* laser_pos     = big[0];
    const float* camera_pos    = big[1];
    const float* laser_origin  = small3[0];
    const float* camera_origin = small3[1];
    float* out = (float*)d_out;

    k_pre<<<1, 128>>>(laser_pos, camera_pos, laser_origin, camera_origin, idxp);
    k_main<<<MC * RR, 128>>>(dirs, out);
    k_fix<<<dim3(MC, 8), 128>>>(out);
}

// round 4
// speedup vs baseline: 1.2316x; 1.2316x over previous
#include <cuda_runtime.h>
#include <cuda_bf16.h>

#define HNUM 256
#define WNUM 256
#define MC   128
#define RR   1024
#define TT   512
#define BINL 0.02f

// output layout (all float32, concat of reference tuple, row-major each)
#define N_MR   (MC * RR)                         // 131072
#define OFF_O  0LL
#define OFF_D  ((long long)N_MR * 3)
#define OFF_T  ((long long)N_MR * 6)
#define OFF_XY ((long long)N_MR * 6 + (long long)N_MR * TT)

// per-m scratch (allocation-free: device globals)
__device__ int   g_y[MC], g_x[MC], g_flag[MC];
__device__ float g_org[MC][3], g_lvec[MC][3];
__device__ float g_l[MC], g_eff[MC], g_d1d4[MC];

__global__ void k_pre(const float* __restrict__ laser_pos,
                      const float* __restrict__ camera_pos,
                      const float* __restrict__ laser_origin,
                      const float* __restrict__ camera_origin,
                      const int* __restrict__ idx_perm)
{
    int m = threadIdx.x;
    if (m >= MC) return;

    int idx = idx_perm[m];
    if (idx < 0) idx = 0;
    if (idx >= HNUM * WNUM) idx = HNUM * WNUM - 1;
    int y = idx / WNUM;
    int x = idx % WNUM;
    if (m == 0) { y = HNUM / 2; x = WNUM / 2; }

    const float* lp = laser_pos  + ((long long)y * WNUM + x) * 3;
    const float* cp = camera_pos + ((long long)y * WNUM + x) * 3;
    float lp0 = lp[0], lp1 = lp[1], lp2 = lp[2];
    float cp0 = cp[0], cp1 = cp[1], cp2 = cp[2];

    float a0 = lp0 - laser_origin[0];
    float a1 = lp1 - laser_origin[1];
    float a2 = lp2 - laser_origin[2];
    float d1 = sqrtf(a0 * a0 + a1 * a1 + a2 * a2);

    float b0 = cp0 - camera_origin[0];
    float b1 = cp1 - camera_origin[1];
    float b2 = cp2 - camera_origin[2];
    float d4 = sqrtf(b0 * b0 + b1 * b1 + b2 * b2);

    float v0 = lp0 - cp0, v1 = lp1 - cp1, v2 = lp2 - cp2;
    float l  = sqrtf(v0 * v0 + v1 * v1 + v2 * v2);
    float inv = 1.0f / fmaxf(l, 1e-12f);

    float off_f = ceilf((l - (d1 + d4)) / BINL);
    int   off   = (int)off_f;
    int   eff   = ((off % TT) + TT) % TT;

    g_y[m] = y;  g_x[m] = x;
    g_org[m][0] = cp0; g_org[m][1] = cp1; g_org[m][2] = cp2;
    g_lvec[m][0] = v0 * inv; g_lvec[m][1] = v1 * inv; g_lvec[m][2] = v2 * inv;
    g_l[m]    = l;
    g_eff[m]  = (float)eff;
    g_d1d4[m] = d1 + d4;
    g_flag[m] = 0;
}

__global__ void __launch_bounds__(128) k_main(const float* __restrict__ dirs,
                                              float* __restrict__ out)
{
    int b = blockIdx.x;            // 0 .. MC*RR-1
    int m = b >> 10;               // / RR
    int r = b & (RR - 1);
    int tid = threadIdx.x;         // 128 threads, 4 tau-bins each

    float l   = g_l[m];
    float eff = g_eff[m];
    float lv0 = g_lvec[m][0], lv1 = g_lvec[m][1], lv2 = g_lvec[m][2];
    float e0  = dirs[r * 3 + 0], e1 = dirs[r * 3 + 1], e2 = dirs[r * 3 + 2];

    // small outputs first (independent of main loop)
    if (tid < 3) {
        out[OFF_O + (long long)b * 3 + tid] = g_org[m][tid];
        out[OFF_D + (long long)b * 3 + tid] = (tid == 0 ? e0 : (tid == 1 ? e1 : e2));
    }
    if (tid < 2) {
        out[OFF_XY + (long long)b * 2 + tid] = (float)(tid == 0 ? g_y[m] : g_x[m]);
    }

    // dx strict left-to-right f32 (no FMA) — keeps dy-NaN boundary bit-identical to ref
    float dx  = __fadd_rn(__fadd_rn(__fmul_rn(e0, lv0), __fmul_rn(e1, lv1)),
                          __fmul_rn(e2, lv2));
    float dx2 = __fmul_rn(dx, dx);
    float dy  = sqrtf(__fsub_rn(1.0f, dx2));   // NaN if dx^2 > 1 (must propagate)
    float dy2 = __fmul_rn(dy, dy);
    float l2  = l * l;
    float dxl = dx * l;
    float a2x = 2.0f * dx2;                    // folded "2*" from den
    float b2y = 2.0f * dy2;                    // NaN if dy NaN -> den NaN -> q NaN (correct)

    int t0 = tid * 4;
    float res[4];
    bool anynan = false;

#pragma unroll
    for (int j = 0; j < 4; ++j) {
        float tf   = (float)(t0 + j);
        float tau  = BINL * fmaxf(tf, eff);
        float tau2 = tau * tau;
        float diff = tau2 - l2;
        float num  = (dxl + tau) * diff;
        float den  = fmaf(a2x, diff, b2y * tau2);
        float q    = __fdividef(num, den);     // MUFU.RCP+FMUL; 0/0 -> NaN, NaN den -> NaN
        anynan |= !(q == q);
        res[j] = q;
    }

    __stcs((float4*)(out + OFF_T + (long long)b * TT + t0),
           make_float4(res[0], res[1], res[2], res[3]));

    // per-m NaN flag without a block barrier (idempotent racy store)
    if (__any_sync(0xffffffffu, (int)anynan)) {
        if ((tid & 31) == 0) g_flag[m] = 1;
    }
}

// Rewrite whole (R,T) slab of flagged rows with t_conf (rare / usually no-op).
__global__ void __launch_bounds__(128) k_fix(float* __restrict__ out)
{
    int m = blockIdx.x;
    if (!g_flag[m]) return;

    float d1d4 = g_d1d4[m];
    int tid = threadIdx.x;
    int t0 = tid * 4;
    float res[4];
#pragma unroll
    for (int j = 0; j < 4; ++j) {
        float tau0 = __fmul_rn((float)(t0 + j), BINL);
        float d    = __fsub_rn(tau0, d1d4);
        if (d <= 0.0f) d = 1e-6f;
        res[j] = __fmul_rn(d, 0.5f);
    }
    float4 v4 = make_float4(res[0], res[1], res[2], res[3]);
    for (int r = blockIdx.y; r < RR; r += gridDim.y) {
        *(float4*)(out + OFF_T + ((long long)m * RR + r) * TT + t0) = v4;
    }
}

extern "C" void kernel_launch(void* const* d_in, const int* in_sizes, int n_in,
                              void* d_out, int out_size)
{
    // Identify inputs by element count (robust to metadata ordering)
    const float* big[2]    = {nullptr, nullptr};
    const float* small3[2] = {nullptr, nullptr};
    const float* dirs      = nullptr;
    const int*   idxp      = nullptr;
    int nbig = 0, nsmall = 0;
    for (int i = 0; i < n_in; ++i) {
        int s = in_sizes[i];
        if (s == HNUM * WNUM * 3) { if (nbig < 2) big[nbig++] = (const float*)d_in[i]; }
        else if (s == 3)          { if (nsmall < 2) small3[nsmall++] = (const float*)d_in[i]; }
        else if (s == RR * 3)     { dirs = (const float*)d_in[i]; }
        else if (s == MC)         { idxp = (const int*)d_in[i]; }
    }
    float* out = (float*)d_out;

    k_pre<<<1, 128>>>(big[0], big[1], small3[0], small3[1], idxp);
    k_main<<<MC * RR, 128>>>(dirs, out);
    k_fix<<<dim3(MC, 8), 128>>>(out);
}